// round 1
// baseline (speedup 1.0000x reference)
#include <cuda_runtime.h>
#include <math.h>

#define BATCH 8
#define FEAT 512
#define NUM 512
#define KK 32
#define NSPLIT 4

// ---------------- device scratch (static, allocation-free) ----------------
__device__ float g_a[BATCH * NUM * KK];              // softmax assignments a[b][n][k]
__device__ float g_axp[NSPLIT * BATCH * FEAT * KK];  // partial ax  [s][b][f][k]
__device__ float g_ax2p[NSPLIT * BATCH * FEAT * KK]; // partial ax2 [s][b][f][k]
__device__ float g_asum[BATCH * KK];                 // asum[b][k]
__device__ float g_ssqp[BATCH * 8 * 2];              // global-norm partials [b][fchunk][fv1/fv2]

__device__ __forceinline__ float wsum(float v) {
#pragma unroll
    for (int o = 16; o; o >>= 1) v += __shfl_xor_sync(0xffffffffu, v, o);
    return v;
}
__device__ __forceinline__ float wmax(float v) {
#pragma unroll
    for (int o = 16; o; o >>= 1) v = fmaxf(v, __shfl_xor_sync(0xffffffffu, v, o));
    return v;
}

// ---------------- K1: logits + softmax --------------------------------------
// grid (16 n-tiles, 8 batch), 256 threads. lane = k, warp owns 4 n's.
// Full-K logits live in registers -> softmax is pure warp shuffles.
__global__ __launch_bounds__(256) void k_softmax(const float* __restrict__ x,
                                                 const float* __restrict__ W,
                                                 const float* __restrict__ bias) {
    __shared__ float W_s[KK][65];   // pad 65: per-lane stride -> conflict-free
    __shared__ float X_s[64][32];   // [f_local][n_local], reads are warp-uniform broadcasts

    const int b    = blockIdx.y;
    const int n0   = blockIdx.x * 32;
    const int tid  = threadIdx.x;
    const int w    = tid >> 5;      // warp id 0..7 -> n subgroup
    const int lane = tid & 31;      // k

    float acc[4] = {0.f, 0.f, 0.f, 0.f};

    for (int t = 0; t < 8; t++) {
        const int fb = t * 64;
        for (int idx = tid; idx < 32 * 64; idx += 256) {
            int k = idx >> 6, fl = idx & 63;
            W_s[k][fl] = W[k * FEAT + fb + fl];
        }
        for (int idx = tid; idx < 64 * 32; idx += 256) {
            int fl = idx >> 5, nl = idx & 31;
            X_s[fl][nl] = x[((size_t)b * FEAT + fb + fl) * NUM + n0 + nl];
        }
        __syncthreads();
#pragma unroll 4
        for (int fl = 0; fl < 64; fl++) {
            float  wv = W_s[lane][fl];                                        // per-lane, conflict-free
            float4 xv = *reinterpret_cast<const float4*>(&X_s[fl][w * 4]);    // warp-uniform broadcast
            acc[0] = fmaf(wv, xv.x, acc[0]);
            acc[1] = fmaf(wv, xv.y, acc[1]);
            acc[2] = fmaf(wv, xv.z, acc[2]);
            acc[3] = fmaf(wv, xv.w, acc[3]);
        }
        __syncthreads();
    }

    const float bv = bias[lane];
#pragma unroll
    for (int j = 0; j < 4; j++) {
        float l = acc[j] + bv;
        float m = wmax(l);
        float e = __expf(l - m);
        float s = wsum(e);
        float a = e / s;
        int   n = n0 + w * 4 + j;
        g_a[((size_t)b * NUM + n) * KK + lane] = a;   // coalesced (k contiguous)
    }
}

// ---------------- K2: ax / ax2 GEMMs (partials over n-splits) ---------------
// grid (8 f-tiles, 4 n-splits, 8 batch) = 256 CTAs, 256 threads.
// lane = f (conflict-free stride-33 LDS), k broadcast via float4 from A_s.
__global__ __launch_bounds__(256) void k_gemm(const float* __restrict__ x) {
    __shared__ float A_s[32][32];
    __shared__ float X_s[64][33];
    __shared__ float X2_s[64][33];

    const int f0  = blockIdx.x * 64;
    const int nb  = blockIdx.y * 128;
    const int b   = blockIdx.z;
    const int tid = threadIdx.x;
    const int w = tid >> 5, lane = tid & 31;
    const int fw = w & 1, kg = w >> 1;
    const int fl = fw * 32 + lane;     // f within tile
    const int kbase = kg * 8;

    float acc1[8] = {0, 0, 0, 0, 0, 0, 0, 0};
    float acc2[8] = {0, 0, 0, 0, 0, 0, 0, 0};

    for (int c = 0; c < 4; c++) {
        const int n0 = nb + c * 32;
        for (int idx = tid; idx < 1024; idx += 256) {
            int nl = idx >> 5, k = idx & 31;
            A_s[nl][k] = g_a[((size_t)b * NUM + n0 + nl) * KK + k];
        }
        for (int idx = tid; idx < 2048; idx += 256) {
            int fr = idx >> 5, nc = idx & 31;
            float v = x[((size_t)b * FEAT + f0 + fr) * NUM + n0 + nc];
            X_s[fr][nc]  = v;
            X2_s[fr][nc] = v * v;   // stage x^2 once, not per-thread
        }
        __syncthreads();
#pragma unroll 2
        for (int nl = 0; nl < 32; nl++) {
            float  xv  = X_s[fl][nl];    // stride 33 -> conflict-free
            float  x2v = X2_s[fl][nl];
            float4 a0 = *reinterpret_cast<const float4*>(&A_s[nl][kbase]);     // broadcast
            float4 a1 = *reinterpret_cast<const float4*>(&A_s[nl][kbase + 4]); // broadcast
            acc1[0] = fmaf(a0.x, xv, acc1[0]);  acc2[0] = fmaf(a0.x, x2v, acc2[0]);
            acc1[1] = fmaf(a0.y, xv, acc1[1]);  acc2[1] = fmaf(a0.y, x2v, acc2[1]);
            acc1[2] = fmaf(a0.z, xv, acc1[2]);  acc2[2] = fmaf(a0.z, x2v, acc2[2]);
            acc1[3] = fmaf(a0.w, xv, acc1[3]);  acc2[3] = fmaf(a0.w, x2v, acc2[3]);
            acc1[4] = fmaf(a1.x, xv, acc1[4]);  acc2[4] = fmaf(a1.x, x2v, acc2[4]);
            acc1[5] = fmaf(a1.y, xv, acc1[5]);  acc2[5] = fmaf(a1.y, x2v, acc2[5]);
            acc1[6] = fmaf(a1.z, xv, acc1[6]);  acc2[6] = fmaf(a1.z, x2v, acc2[6]);
            acc1[7] = fmaf(a1.w, xv, acc1[7]);  acc2[7] = fmaf(a1.w, x2v, acc2[7]);
        }
        __syncthreads();
    }

    const size_t base = (((size_t)blockIdx.y * BATCH + b) * FEAT + f0 + fl) * KK + kbase;
    float4 v;
    v = make_float4(acc1[0], acc1[1], acc1[2], acc1[3]);
    *reinterpret_cast<float4*>(&g_axp[base]) = v;
    v = make_float4(acc1[4], acc1[5], acc1[6], acc1[7]);
    *reinterpret_cast<float4*>(&g_axp[base + 4]) = v;
    v = make_float4(acc2[0], acc2[1], acc2[2], acc2[3]);
    *reinterpret_cast<float4*>(&g_ax2p[base]) = v;
    v = make_float4(acc2[4], acc2[5], acc2[6], acc2[7]);
    *reinterpret_cast<float4*>(&g_ax2p[base + 4]) = v;
}

// ---------------- K3: asum ---------------------------------------------------
__global__ __launch_bounds__(256) void k_asum() {
    __shared__ float red[8][32];
    const int b = blockIdx.x, tid = threadIdx.x;
    const int k = tid & 31, ng = tid >> 5;
    float p = 0.f;
    for (int t = 0; t < 64; t++)
        p += g_a[((size_t)b * NUM + ng * 64 + t) * KK + k];
    red[ng][k] = p;
    __syncthreads();
    if (tid < 32) {
        float s = 0.f;
        for (int g = 0; g < 8; g++) s += red[g][tid];
        g_asum[b * KK + tid] = s;
    }
}

// ---------------- E1: fisher vectors + per-row L2 norm ----------------------
// grid (8 f-chunks, 8 batch), 256 threads. warp = 32 k's of one f.
__global__ __launch_bounds__(256) void k_fv(const float* __restrict__ mu,
                                            const float* __restrict__ sigma,
                                            float* __restrict__ out) {
    __shared__ float s1s[8], s2s[8];
    const int fc = blockIdx.x, b = blockIdx.y;
    const int tid = threadIdx.x, w = tid >> 5, lane = tid & 31;
    const float asv = g_asum[b * KK + lane];
    const size_t ob = (size_t)b * 2 * FEAT * KK;

    float ssq1 = 0.f, ssq2 = 0.f;
    for (int j = 0; j < 8; j++) {
        const int f = fc * 64 + w + 8 * j;
        float ax = 0.f, ax2 = 0.f;
#pragma unroll
        for (int s = 0; s < NSPLIT; s++) {
            size_t po = (((size_t)s * BATCH + b) * FEAT + f) * KK + lane;
            ax  += g_axp[po];
            ax2 += g_ax2p[po];
        }
        float muv = mu[f * KK + lane];
        float sg  = sigma[f * KK + lane];
        float fv1 = (ax - muv * asv) / sg;
        float fv2 = (ax2 - 2.f * muv * ax + muv * muv * asv) / (sg * sg) - asv;

        float n1 = sqrtf(wsum(fv1 * fv1));
        float n2 = sqrtf(wsum(fv2 * fv2));
        float v1 = fv1 / fmaxf(n1, 1e-12f);
        float v2 = fv2 / fmaxf(n2, 1e-12f);
        ssq1 += v1 * v1;
        ssq2 += v2 * v2;
        out[ob + (size_t)f * KK + lane]             = v1;
        out[ob + FEAT * KK + (size_t)f * KK + lane] = v2;
    }
    ssq1 = wsum(ssq1);
    ssq2 = wsum(ssq2);
    if (lane == 0) { s1s[w] = ssq1; s2s[w] = ssq2; }
    __syncthreads();
    if (tid == 0) {
        float t1 = 0.f, t2 = 0.f;
        for (int g = 0; g < 8; g++) { t1 += s1s[g]; t2 += s2s[g]; }
        g_ssqp[(b * 8 + fc) * 2 + 0] = t1;
        g_ssqp[(b * 8 + fc) * 2 + 1] = t2;
    }
}

// ---------------- E2: global L2 scale (deterministic, no atomics) -----------
__global__ __launch_bounds__(256) void k_scale(float* __restrict__ out) {
    __shared__ float sc;
    const int tid = threadIdx.x;
    const int blk = blockIdx.x;         // 256 blocks x 1024 floats; block spans one (b, half)
    const int b    = blk >> 5;          // 32 blocks per batch
    const int half = (blk >> 4) & 1;    // 16 blocks per half
    if (tid == 0) {
        float s = 0.f;
        for (int fcq = 0; fcq < 8; fcq++) s += g_ssqp[(b * 8 + fcq) * 2 + half];
        sc = 1.f / fmaxf(sqrtf(s), 1e-12f);
    }
    __syncthreads();
    float4* o4 = reinterpret_cast<float4*>(out);
    size_t i = (size_t)blk * 256 + tid;
    float4 v = o4[i];
    float s = sc;
    v.x *= s; v.y *= s; v.z *= s; v.w *= s;
    o4[i] = v;
}

// ---------------- launch -----------------------------------------------------
extern "C" void kernel_launch(void* const* d_in, const int* in_sizes, int n_in,
                              void* d_out, int out_size) {
    (void)in_sizes; (void)n_in; (void)out_size;
    const float* x     = (const float*)d_in[0];
    const float* W     = (const float*)d_in[1];
    const float* bias  = (const float*)d_in[2];
    const float* mu    = (const float*)d_in[3];
    const float* sigma = (const float*)d_in[4];
    float* out = (float*)d_out;

    k_softmax<<<dim3(16, 8), 256>>>(x, W, bias);
    k_gemm<<<dim3(8, NSPLIT, 8), 256>>>(x);
    k_asum<<<8, 256>>>();
    k_fv<<<dim3(8, 8), 256>>>(mu, sigma, out);
    k_scale<<<256, 256>>>(out);
}

// round 2
// speedup vs baseline: 1.1363x; 1.1363x over previous
#include <cuda_runtime.h>
#include <math.h>

#define BATCH 8
#define FEAT 512
#define NUM 512
#define KK 32
#define NSPLIT 4

typedef unsigned long long ull;

// ---------------- device scratch (static, allocation-free) ----------------
__device__ float g_a[BATCH * NUM * KK];               // softmax assignments a[b][n][k]
__device__ float g_axp[NSPLIT * BATCH * FEAT * KK];   // partial ax  [s][b][f][k]
__device__ float g_ax2p[NSPLIT * BATCH * FEAT * KK];  // partial ax2 [s][b][f][k]
__device__ float g_asump[BATCH * 16 * KK];            // asum partials per n-tile
__device__ float g_ssqp[BATCH * 64 * 2];              // global-norm partials [b][fg][fv1/fv2]

__device__ __forceinline__ float wsum(float v) {
#pragma unroll
    for (int o = 16; o; o >>= 1) v += __shfl_xor_sync(0xffffffffu, v, o);
    return v;
}
__device__ __forceinline__ float wmax(float v) {
#pragma unroll
    for (int o = 16; o; o >>= 1) v = fmaxf(v, __shfl_xor_sync(0xffffffffu, v, o));
    return v;
}

// packed f32x2 helpers (sm_100+)
__device__ __forceinline__ ull pk(float lo, float hi) {
    ull r;
    asm("mov.b64 %0, {%1, %2};" : "=l"(r) : "f"(lo), "f"(hi));
    return r;
}
__device__ __forceinline__ void upk(float& lo, float& hi, ull v) {
    asm("mov.b64 {%0, %1}, %2;" : "=f"(lo), "=f"(hi) : "l"(v));
}
__device__ __forceinline__ void ffma2(ull& d, ull a, ull b) {
    asm("fma.rn.f32x2 %0, %1, %2, %0;" : "+l"(d) : "l"(a), "l"(b));
}

// ---------------- K1: logits + softmax + asum partials -----------------------
// grid (16 n-tiles, 8 batch), 256 threads. lane = k, warp owns 4 n's (2 f32x2 pairs).
__global__ __launch_bounds__(256) void k_softmax(const float* __restrict__ x,
                                                 const float* __restrict__ W,
                                                 const float* __restrict__ bias) {
    __shared__ float W_s[KK][65];                     // pad 65: conflict-free per-lane stride
    __shared__ __align__(16) float X_s[64][32];       // [f_local][n_local]
    __shared__ float red[8][KK];

    const int b    = blockIdx.y;
    const int n0   = blockIdx.x * 32;
    const int tid  = threadIdx.x;
    const int w    = tid >> 5;      // warp -> n subgroup
    const int lane = tid & 31;      // k

    ull acc01 = 0ULL, acc23 = 0ULL;

    for (int t = 0; t < 8; t++) {
        const int fb = t * 64;
        for (int idx = tid; idx < 32 * 64; idx += 256) {
            int k = idx >> 6, fl = idx & 63;
            W_s[k][fl] = W[k * FEAT + fb + fl];
        }
        for (int idx = tid; idx < 64 * 32; idx += 256) {
            int fl = idx >> 5, nl = idx & 31;
            X_s[fl][nl] = x[((size_t)b * FEAT + fb + fl) * NUM + n0 + nl];
        }
        __syncthreads();
#pragma unroll 4
        for (int fl = 0; fl < 64; fl++) {
            float wv = W_s[lane][fl];                                            // conflict-free
            ull   wvv = pk(wv, wv);
            ulonglong2 xp = *reinterpret_cast<const ulonglong2*>(&X_s[fl][w * 4]); // broadcast
            ffma2(acc01, wvv, xp.x);
            ffma2(acc23, wvv, xp.y);
        }
        __syncthreads();
    }

    float l[4];
    upk(l[0], l[1], acc01);
    upk(l[2], l[3], acc23);

    const float bv = bias[lane];
    float pa = 0.f;
#pragma unroll
    for (int j = 0; j < 4; j++) {
        float lg = l[j] + bv;
        float m = wmax(lg);
        float e = __expf(lg - m);
        float s = wsum(e);
        float a = e / s;
        int   n = n0 + w * 4 + j;
        g_a[((size_t)b * NUM + n) * KK + lane] = a;   // coalesced (k contiguous)
        pa += a;
    }
    red[w][lane] = pa;
    __syncthreads();
    if (tid < 32) {
        float s = 0.f;
#pragma unroll
        for (int g = 0; g < 8; g++) s += red[g][tid];
        g_asump[((size_t)b * 16 + blockIdx.x) * KK + tid] = s;   // per-tile asum partial
    }
}

// ---------------- K2: ax / ax2 GEMMs with packed f32x2 FMAs ------------------
// grid (8 f-tiles, 4 n-splits, 8 batch) = 256 CTAs, 256 threads.
// lane = f (stride-33 conflict-free), k-PAIRS loaded as native b64 broadcasts.
__global__ __launch_bounds__(256) void k_gemm(const float* __restrict__ x) {
    __shared__ __align__(16) float A_s[32][32];
    __shared__ float X_s[64][33];
    __shared__ float X2_s[64][33];

    const int f0  = blockIdx.x * 64;
    const int nb  = blockIdx.y * 128;
    const int b   = blockIdx.z;
    const int tid = threadIdx.x;
    const int w = tid >> 5, lane = tid & 31;
    const int fw = w & 1, kg = w >> 1;
    const int fl = fw * 32 + lane;     // f within tile
    const int kbase = kg * 8;          // 8 k's = 4 packed pairs per thread

    ull acc1[4] = {0ULL, 0ULL, 0ULL, 0ULL};   // ax  pairs (k, k+1)
    ull acc2[4] = {0ULL, 0ULL, 0ULL, 0ULL};   // ax2 pairs

    for (int c = 0; c < 4; c++) {
        const int n0 = nb + c * 32;
        for (int idx = tid; idx < 1024; idx += 256) {
            int nl = idx >> 5, k = idx & 31;
            A_s[nl][k] = g_a[((size_t)b * NUM + n0 + nl) * KK + k];
        }
        for (int idx = tid; idx < 2048; idx += 256) {
            int fr = idx >> 5, nc = idx & 31;
            float v = x[((size_t)b * FEAT + f0 + fr) * NUM + n0 + nc];
            X_s[fr][nc]  = v;
            X2_s[fr][nc] = v * v;
        }
        __syncthreads();
#pragma unroll 4
        for (int nl = 0; nl < 32; nl++) {
            float xv  = X_s[fl][nl];    // stride 33 -> conflict-free
            float x2v = X2_s[fl][nl];
            ull xvv  = pk(xv, xv);
            ull x2vv = pk(x2v, x2v);
            ulonglong2 a01 = *reinterpret_cast<const ulonglong2*>(&A_s[nl][kbase]);     // broadcast
            ulonglong2 a23 = *reinterpret_cast<const ulonglong2*>(&A_s[nl][kbase + 4]); // broadcast
            ffma2(acc1[0], a01.x, xvv);  ffma2(acc2[0], a01.x, x2vv);
            ffma2(acc1[1], a01.y, xvv);  ffma2(acc2[1], a01.y, x2vv);
            ffma2(acc1[2], a23.x, xvv);  ffma2(acc2[2], a23.x, x2vv);
            ffma2(acc1[3], a23.y, xvv);  ffma2(acc2[3], a23.y, x2vv);
        }
        __syncthreads();
    }

    // pairs are k-contiguous -> store directly as 128-bit chunks
    const size_t base = (((size_t)blockIdx.y * BATCH + b) * FEAT + f0 + fl) * KK + kbase;
    *reinterpret_cast<ulonglong2*>(&g_axp[base])      = make_ulonglong2(acc1[0], acc1[1]);
    *reinterpret_cast<ulonglong2*>(&g_axp[base + 4])  = make_ulonglong2(acc1[2], acc1[3]);
    *reinterpret_cast<ulonglong2*>(&g_ax2p[base])     = make_ulonglong2(acc2[0], acc2[1]);
    *reinterpret_cast<ulonglong2*>(&g_ax2p[base + 4]) = make_ulonglong2(acc2[2], acc2[3]);
}

// ---------------- E1: fisher vectors + per-row L2 norm ----------------------
// grid (64 f-groups, 8 batch), 256 threads. ONE f per warp -> no serial j loop.
__global__ __launch_bounds__(256) void k_fv(const float* __restrict__ mu,
                                            const float* __restrict__ sigma,
                                            float* __restrict__ out) {
    __shared__ float s1s[8], s2s[8];
    const int fg = blockIdx.x, b = blockIdx.y;
    const int tid = threadIdx.x, w = tid >> 5, lane = tid & 31;
    const int f = fg * 8 + w;

    // asum[b][k] from 16 per-tile partials (L2-hot)
    float asv = 0.f;
#pragma unroll
    for (int t = 0; t < 16; t++) asv += g_asump[((size_t)b * 16 + t) * KK + lane];

    float ax = 0.f, ax2 = 0.f;
#pragma unroll
    for (int s = 0; s < NSPLIT; s++) {
        size_t po = (((size_t)s * BATCH + b) * FEAT + f) * KK + lane;
        ax  += g_axp[po];
        ax2 += g_ax2p[po];
    }
    float muv = mu[f * KK + lane];
    float sg  = sigma[f * KK + lane];
    float fv1 = (ax - muv * asv) / sg;
    float fv2 = (ax2 - 2.f * muv * ax + muv * muv * asv) / (sg * sg) - asv;

    float n1 = sqrtf(wsum(fv1 * fv1));
    float n2 = sqrtf(wsum(fv2 * fv2));
    float v1 = fv1 / fmaxf(n1, 1e-12f);
    float v2 = fv2 / fmaxf(n2, 1e-12f);

    const size_t ob = (size_t)b * 2 * FEAT * KK;
    out[ob + (size_t)f * KK + lane]             = v1;
    out[ob + FEAT * KK + (size_t)f * KK + lane] = v2;

    float ssq1 = wsum(v1 * v1);
    float ssq2 = wsum(v2 * v2);
    if (lane == 0) { s1s[w] = ssq1; s2s[w] = ssq2; }
    __syncthreads();
    if (tid == 0) {
        float t1 = 0.f, t2 = 0.f;
#pragma unroll
        for (int g = 0; g < 8; g++) { t1 += s1s[g]; t2 += s2s[g]; }
        g_ssqp[((size_t)b * 64 + fg) * 2 + 0] = t1;
        g_ssqp[((size_t)b * 64 + fg) * 2 + 1] = t2;
    }
}

// ---------------- E2: global L2 scale (deterministic, no atomics) -----------
__global__ __launch_bounds__(256) void k_scale(float* __restrict__ out) {
    __shared__ float ps[64];
    __shared__ float sc;
    const int tid = threadIdx.x;
    const int blk = blockIdx.x;         // 256 blocks x 1024 floats
    const int b    = blk >> 5;          // 32 blocks per batch
    const int half = (blk >> 4) & 1;    // 16 blocks per half
    if (tid < 64) ps[tid] = g_ssqp[((size_t)b * 64 + tid) * 2 + half];
    __syncthreads();
    if (tid == 0) {
        float s = 0.f;
#pragma unroll
        for (int i = 0; i < 64; i++) s += ps[i];
        sc = 1.f / fmaxf(sqrtf(s), 1e-12f);
    }
    __syncthreads();
    float4* o4 = reinterpret_cast<float4*>(out);
    size_t i = (size_t)blk * 256 + tid;
    float4 v = o4[i];
    float s = sc;
    v.x *= s; v.y *= s; v.z *= s; v.w *= s;
    o4[i] = v;
}

// ---------------- launch -----------------------------------------------------
extern "C" void kernel_launch(void* const* d_in, const int* in_sizes, int n_in,
                              void* d_out, int out_size) {
    (void)in_sizes; (void)n_in; (void)out_size;
    const float* x     = (const float*)d_in[0];
    const float* W     = (const float*)d_in[1];
    const float* bias  = (const float*)d_in[2];
    const float* mu    = (const float*)d_in[3];
    const float* sigma = (const float*)d_in[4];
    float* out = (float*)d_out;

    k_softmax<<<dim3(16, 8), 256>>>(x, W, bias);
    k_gemm<<<dim3(8, NSPLIT, 8), 256>>>(x);
    k_fv<<<dim3(64, 8), 256>>>(mu, sigma, out);
    k_scale<<<256, 256>>>(out);
}

// round 3
// speedup vs baseline: 1.3136x; 1.1560x over previous
#include <cuda_runtime.h>
#include <math.h>

#define BATCH 8
#define FEAT 512
#define NUM 512
#define KK 32
#define NSPLIT 4

typedef unsigned long long ull;

// ---------------- device scratch (static, allocation-free) ----------------
__device__ float g_a[BATCH * NUM * KK];               // softmax assignments a[b][n][k]
__device__ float g_axp[NSPLIT * BATCH * FEAT * KK];   // partial ax  [s][b][f][k]
__device__ float g_ax2p[NSPLIT * BATCH * FEAT * KK];  // partial ax2 [s][b][f][k]
__device__ float g_asump[BATCH * 16 * KK];            // asum partials per n-tile
__device__ float g_ssqp[BATCH * 64 * 2];              // global-norm partials [b][fg][fv1/fv2]
__device__ unsigned g_bar_main = 0;                   // grid barrier for k_main
__device__ unsigned g_bar_fv = 0;                     // grid barrier for k_fv

__device__ __forceinline__ float wsum(float v) {
#pragma unroll
    for (int o = 16; o; o >>= 1) v += __shfl_xor_sync(0xffffffffu, v, o);
    return v;
}
__device__ __forceinline__ float wmax(float v) {
#pragma unroll
    for (int o = 16; o; o >>= 1) v = fmaxf(v, __shfl_xor_sync(0xffffffffu, v, o));
    return v;
}

// packed f32x2 helpers (sm_100+)
__device__ __forceinline__ ull pk(float lo, float hi) {
    ull r;
    asm("mov.b64 %0, {%1, %2};" : "=l"(r) : "f"(lo), "f"(hi));
    return r;
}
__device__ __forceinline__ void upk(float& lo, float& hi, ull v) {
    asm("mov.b64 {%0, %1}, %2;" : "=f"(lo), "=f"(hi) : "l"(v));
}
__device__ __forceinline__ void ffma2(ull& d, ull a, ull b) {
    asm("fma.rn.f32x2 %0, %1, %2, %0;" : "+l"(d) : "l"(a), "l"(b));
}

// shared-memory phase union (softmax phase vs gemm phase)
struct P1 {
    float W_s[KK][65];     // pad 65: conflict-free per-lane stride
    float X_s[64][32];     // [f_local][n_local]
    float red[8][KK];
};
struct P2 {
    float A_s[32][32];
    float X_s[64][33];     // stride 33: conflict-free per-lane f
    float X2_s[64][33];
};
union SMU {
    P1 p1;
    P2 p2;
};

// ---------------- K_MAIN: softmax phase -> grid barrier -> gemm phase --------
// grid 256, block 256, all CTAs co-resident (occ >= 2 guaranteed by launch_bounds).
__global__ __launch_bounds__(256, 2) void k_main(const float* __restrict__ x,
                                                 const float* __restrict__ W,
                                                 const float* __restrict__ bias) {
    __shared__ __align__(16) SMU sm;
    const int tid  = threadIdx.x;
    const int w    = tid >> 5;
    const int lane = tid & 31;
    const int bx   = blockIdx.x;

    // reset k_fv's barrier counter for this replay (stream order: k_main < k_fv)
    if (bx == 0 && tid == 0) *((volatile unsigned*)&g_bar_fv) = 0u;

    // ================= PHASE 1: logits + softmax + asum partials =============
    if (bx < 128) {
        const int b  = bx >> 4;
        const int n0 = (bx & 15) * 32;

        ull acc01 = 0ULL, acc23 = 0ULL;

        for (int t = 0; t < 8; t++) {
            const int fb = t * 64;
            for (int idx = tid; idx < 32 * 64; idx += 256) {
                int k = idx >> 6, fl = idx & 63;
                sm.p1.W_s[k][fl] = W[k * FEAT + fb + fl];
            }
            for (int idx = tid; idx < 64 * 32; idx += 256) {
                int fl = idx >> 5, nl = idx & 31;
                sm.p1.X_s[fl][nl] = x[((size_t)b * FEAT + fb + fl) * NUM + n0 + nl];
            }
            __syncthreads();
#pragma unroll 4
            for (int fl = 0; fl < 64; fl++) {
                float wv = sm.p1.W_s[lane][fl];                                          // conflict-free
                ull   wvv = pk(wv, wv);
                ulonglong2 xp = *reinterpret_cast<const ulonglong2*>(&sm.p1.X_s[fl][w * 4]); // broadcast
                ffma2(acc01, wvv, xp.x);
                ffma2(acc23, wvv, xp.y);
            }
            __syncthreads();
        }

        float l[4];
        upk(l[0], l[1], acc01);
        upk(l[2], l[3], acc23);

        const float bv = bias[lane];
        float pa = 0.f;
#pragma unroll
        for (int j = 0; j < 4; j++) {
            float lg = l[j] + bv;
            float m = wmax(lg);
            float e = __expf(lg - m);
            float s = wsum(e);
            float a = e / s;
            int   n = n0 + w * 4 + j;
            g_a[((size_t)b * NUM + n) * KK + lane] = a;   // coalesced (k contiguous)
            pa += a;
        }
        sm.p1.red[w][lane] = pa;
        __syncthreads();
        if (tid < 32) {
            float s = 0.f;
#pragma unroll
            for (int g = 0; g < 8; g++) s += sm.p1.red[g][tid];
            g_asump[((size_t)b * 16 + (bx & 15)) * KK + tid] = s;
        }
    }

    // ================= GRID BARRIER ===========================================
    __threadfence();     // release all this thread's g_a / g_asump stores
    __syncthreads();
    if (tid == 0) {
        atomicAdd(&g_bar_main, 1u);
        while (atomicAdd(&g_bar_main, 0u) < 256u) __nanosleep(64);
        __threadfence();
    }
    __syncthreads();

    // ================= PHASE 2: ax / ax2 GEMM partials ========================
    {
        const int ft = bx & 7;
        const int s  = (bx >> 3) & 3;
        const int b  = bx >> 5;
        const int f0 = ft * 64;
        const int nb = s * 128;
        const int fw = w & 1, kg = w >> 1;
        const int fl = fw * 32 + lane;     // f within tile
        const int kbase = kg * 8;          // 8 k's = 4 packed pairs per thread

        ull acc1[4] = {0ULL, 0ULL, 0ULL, 0ULL};
        ull acc2[4] = {0ULL, 0ULL, 0ULL, 0ULL};

        for (int c = 0; c < 4; c++) {
            const int n0 = nb + c * 32;
            __syncthreads();   // protect smem union reuse across c-iters and phases
            for (int idx = tid; idx < 1024; idx += 256) {
                int nl = idx >> 5, k = idx & 31;
                sm.p2.A_s[nl][k] = g_a[((size_t)b * NUM + n0 + nl) * KK + k];
            }
            for (int idx = tid; idx < 2048; idx += 256) {
                int fr = idx >> 5, nc = idx & 31;
                float v = x[((size_t)b * FEAT + f0 + fr) * NUM + n0 + nc];
                sm.p2.X_s[fr][nc]  = v;
                sm.p2.X2_s[fr][nc] = v * v;
            }
            __syncthreads();
#pragma unroll 4
            for (int nl = 0; nl < 32; nl++) {
                float xv  = sm.p2.X_s[fl][nl];    // stride 33 -> conflict-free
                float x2v = sm.p2.X2_s[fl][nl];
                ull xvv  = pk(xv, xv);
                ull x2vv = pk(x2v, x2v);
                ulonglong2 a01 = *reinterpret_cast<const ulonglong2*>(&sm.p2.A_s[nl][kbase]);     // broadcast
                ulonglong2 a23 = *reinterpret_cast<const ulonglong2*>(&sm.p2.A_s[nl][kbase + 4]); // broadcast
                ffma2(acc1[0], a01.x, xvv);  ffma2(acc2[0], a01.x, x2vv);
                ffma2(acc1[1], a01.y, xvv);  ffma2(acc2[1], a01.y, x2vv);
                ffma2(acc1[2], a23.x, xvv);  ffma2(acc2[2], a23.x, x2vv);
                ffma2(acc1[3], a23.y, xvv);  ffma2(acc2[3], a23.y, x2vv);
            }
        }

        const size_t base = (((size_t)s * BATCH + b) * FEAT + f0 + fl) * KK + kbase;
        *reinterpret_cast<ulonglong2*>(&g_axp[base])      = make_ulonglong2(acc1[0], acc1[1]);
        *reinterpret_cast<ulonglong2*>(&g_axp[base + 4])  = make_ulonglong2(acc1[2], acc1[3]);
        *reinterpret_cast<ulonglong2*>(&g_ax2p[base])     = make_ulonglong2(acc2[0], acc2[1]);
        *reinterpret_cast<ulonglong2*>(&g_ax2p[base + 4]) = make_ulonglong2(acc2[2], acc2[3]);
    }
}

// ---------------- K_FV: fisher vectors + row norm -> barrier -> global scale -
// grid 512 (b*64+fg), block 256, one f per warp. occ >= 4 => all co-resident.
__global__ __launch_bounds__(256, 4) void k_fv(const float* __restrict__ mu,
                                               const float* __restrict__ sigma,
                                               float* __restrict__ out) {
    __shared__ float s1s[8], s2s[8];
    __shared__ float scs[2];
    const int bx = blockIdx.x;
    const int b  = bx >> 6;
    const int fg = bx & 63;
    const int tid = threadIdx.x, w = tid >> 5, lane = tid & 31;
    const int f = fg * 8 + w;

    // reset k_main's barrier counter for the NEXT replay (k_main this replay is done)
    if (bx == 0 && tid == 0) *((volatile unsigned*)&g_bar_main) = 0u;

    // asum[b][k] from 16 per-tile partials (L2-hot)
    float asv = 0.f;
#pragma unroll
    for (int t = 0; t < 16; t++) asv += g_asump[((size_t)b * 16 + t) * KK + lane];

    float ax = 0.f, ax2 = 0.f;
#pragma unroll
    for (int s = 0; s < NSPLIT; s++) {
        size_t po = (((size_t)s * BATCH + b) * FEAT + f) * KK + lane;
        ax  += g_axp[po];
        ax2 += g_ax2p[po];
    }
    float muv = mu[f * KK + lane];
    float sg  = sigma[f * KK + lane];
    float fv1 = (ax - muv * asv) / sg;
    float fv2 = (ax2 - 2.f * muv * ax + muv * muv * asv) / (sg * sg) - asv;

    float n1 = sqrtf(wsum(fv1 * fv1));
    float n2 = sqrtf(wsum(fv2 * fv2));
    float v1 = fv1 / fmaxf(n1, 1e-12f);
    float v2 = fv2 / fmaxf(n2, 1e-12f);

    float ssq1 = wsum(v1 * v1);
    float ssq2 = wsum(v2 * v2);
    if (lane == 0) { s1s[w] = ssq1; s2s[w] = ssq2; }
    __syncthreads();
    if (tid == 0) {
        float t1 = 0.f, t2 = 0.f;
#pragma unroll
        for (int g = 0; g < 8; g++) { t1 += s1s[g]; t2 += s2s[g]; }
        g_ssqp[((size_t)b * 64 + fg) * 2 + 0] = t1;
        g_ssqp[((size_t)b * 64 + fg) * 2 + 1] = t2;
        __threadfence();   // release partial stores
        atomicAdd(&g_bar_fv, 1u);
        while (atomicAdd(&g_bar_fv, 0u) < 512u) __nanosleep(64);
        __threadfence();
    }
    __syncthreads();

    // global scale per (b, half); warps 0/1 each reduce 64 partials in fixed order
    if (w < 2) {
        float s = g_ssqp[((size_t)b * 64 + lane) * 2 + w]
                + g_ssqp[((size_t)b * 64 + 32 + lane) * 2 + w];
        s = wsum(s);
        if (lane == 0) scs[w] = 1.f / fmaxf(sqrtf(s), 1e-12f);
    }
    __syncthreads();

    const size_t ob = (size_t)b * 2 * FEAT * KK;
    out[ob + (size_t)f * KK + lane]             = v1 * scs[0];
    out[ob + FEAT * KK + (size_t)f * KK + lane] = v2 * scs[1];
}

// ---------------- launch -----------------------------------------------------
extern "C" void kernel_launch(void* const* d_in, const int* in_sizes, int n_in,
                              void* d_out, int out_size) {
    (void)in_sizes; (void)n_in; (void)out_size;
    const float* x     = (const float*)d_in[0];
    const float* W     = (const float*)d_in[1];
    const float* bias  = (const float*)d_in[2];
    const float* mu    = (const float*)d_in[3];
    const float* sigma = (const float*)d_in[4];
    float* out = (float*)d_out;

    k_main<<<256, 256>>>(x, W, bias);
    k_fv<<<512, 256>>>(mu, sigma, out);
}